// round 14
// baseline (speedup 1.0000x reference)
#include <cuda_runtime.h>
#include <cuda_fp16.h>
#include <cuda_bf16.h>

// PoseProjection: fused rigid-transform trilinear resample.
// CROP = (X=96, Y=96, Z=48), B=8, C=32, VOXEL_SIZE=0.0625 (1/v = 16).
// (ix,iy,iz) = T[:3,:3]*(w,h,d) + T[:3,3]*16,  T = inv(current)@historical.
// Output (concat f32): feat[8,32,48,96,96] | sdf | occ | grid[8,48,96,96,3]
//
// features transposed to channel-last fp16 [B,DHW,32]: each corner's 32
// channels = 64B; the x-adjacent corner PAIR = one contiguous 128B line ->
// 1 L1 wavefront per (voxel, corner-pair). Partial sums over even/odd
// corners combined via shfl.xor(4).

#define Bn   8
#define Cn   32
#define Dd   48
#define Hh   96
#define Ww   96
#define HW   (Hh * Ww)          // 9216
#define DHW  (Dd * HW)          // 442368
#define FEATN ((size_t)Bn * Cn * DHW)
#define SDFN  ((size_t)Bn * DHW)

#define VPB  64                 // voxels per block (feat_gather)

__device__ float  g_M[Bn][12];
__device__ __half g_featT[(size_t)Bn * DHW * Cn];    // [B][DHW][32] fp16
__device__ float2 g_soT[(size_t)Bn * DHW];           // [B][DHW] {sdf, occ}

// ---------------------------------------------------------------------------
// Setup: T = inv(current) @ historical (Gauss-Jordan w/ pivoting).
// ---------------------------------------------------------------------------
__global__ void setup_kernel(const float* __restrict__ hist,
                             const float* __restrict__ cur) {
    int b = threadIdx.x;
    if (b >= Bn) return;

    float A[4][4], Inv[4][4];
    for (int i = 0; i < 4; i++)
        for (int j = 0; j < 4; j++) {
            A[i][j]   = cur[b * 16 + i * 4 + j];
            Inv[i][j] = (i == j) ? 1.f : 0.f;
        }
    for (int c = 0; c < 4; c++) {
        int p = c; float mx = fabsf(A[c][c]);
        for (int r = c + 1; r < 4; r++) {
            float v = fabsf(A[r][c]);
            if (v > mx) { mx = v; p = r; }
        }
        if (p != c)
            for (int j = 0; j < 4; j++) {
                float t = A[c][j]; A[c][j] = A[p][j]; A[p][j] = t;
                t = Inv[c][j]; Inv[c][j] = Inv[p][j]; Inv[p][j] = t;
            }
        float f = 1.0f / A[c][c];
        for (int j = 0; j < 4; j++) { A[c][j] *= f; Inv[c][j] *= f; }
        for (int r = 0; r < 4; r++) {
            if (r == c) continue;
            float g = A[r][c];
            for (int j = 0; j < 4; j++) {
                A[r][j]   -= g * A[c][j];
                Inv[r][j] -= g * Inv[c][j];
            }
        }
    }
    for (int i = 0; i < 3; i++)
        for (int j = 0; j < 4; j++) {
            float s = 0.f;
            for (int k = 0; k < 4; k++)
                s += Inv[i][k] * hist[b * 16 + k * 4 + j];
            g_M[b][i * 4 + j] = (j == 3) ? s * 16.0f : s;
        }
}

// ---------------------------------------------------------------------------
// Kernel 1a: transpose feat [B,32,DHW] f32 -> featT [B,DHW,32] f16.
// Tile = 32 channels x 64 voxels.
// ---------------------------------------------------------------------------
__global__ void __launch_bounds__(256)
transpose_kernel(const float* __restrict__ feat) {
    __shared__ float s[32][65];
    int b  = blockIdx.y;
    int n0 = blockIdx.x * 64;
    int tid = threadIdx.x;

    // load: thread (r = channel, q): two float4 -> 8 voxels
    {
        int r = tid >> 3;           // 0..31
        int q = tid & 7;            // 0..7
        const float* fp = feat + (size_t)b * Cn * DHW + (size_t)r * DHW + n0 + q * 8;
        float4 v0 = *(const float4*)(fp);
        float4 v1 = *(const float4*)(fp + 4);
        s[r][q * 8 + 0] = v0.x; s[r][q * 8 + 1] = v0.y;
        s[r][q * 8 + 2] = v0.z; s[r][q * 8 + 3] = v0.w;
        s[r][q * 8 + 4] = v1.x; s[r][q * 8 + 5] = v1.y;
        s[r][q * 8 + 6] = v1.z; s[r][q * 8 + 7] = v1.w;
    }
    __syncthreads();

    // store: thread (vox 0..63, part 0..3): 8 channels -> 8 halves = 16B
    {
        int vox  = tid >> 2;        // 0..63
        int part = tid & 3;         // 0..3
        int c0 = part * 8;
        __half2 h[4];
        #pragma unroll
        for (int i = 0; i < 4; i++)
            h[i] = __floats2half2_rn(s[c0 + 2 * i][vox], s[c0 + 2 * i + 1][vox]);
        uint4 u = make_uint4(*(unsigned*)&h[0], *(unsigned*)&h[1],
                             *(unsigned*)&h[2], *(unsigned*)&h[3]);
        char* dst = (char*)g_featT + ((size_t)b * DHW + n0 + vox) * (Cn * 2) + part * 16;
        *(uint4*)dst = u;
    }
}

// ---------------------------------------------------------------------------
// Kernel 1b: interleave sdf/occ -> float2.
// ---------------------------------------------------------------------------
__global__ void __launch_bounds__(256)
interleave_kernel(const float* __restrict__ sdf,
                  const float* __restrict__ occ) {
    size_t i = (size_t)blockIdx.x * blockDim.x + threadIdx.x;
    if (i < SDFN) g_soT[i] = make_float2(sdf[i], occ[i]);
}

// ---------------------------------------------------------------------------
// Corner computation.
// ---------------------------------------------------------------------------
__device__ __forceinline__ void corners(const float* __restrict__ M,
                                        int w, int h, int d,
                                        int off[8], float wgt[8],
                                        float& ix, float& iy, float& iz) {
    float fw = (float)w, fh = (float)h, fd = (float)d;
    ix = fmaf(M[0], fw, fmaf(M[1], fh, fmaf(M[2],  fd, M[3])));
    iy = fmaf(M[4], fw, fmaf(M[5], fh, fmaf(M[6],  fd, M[7])));
    iz = fmaf(M[8], fw, fmaf(M[9], fh, fmaf(M[10], fd, M[11])));

    float x0f = floorf(ix), y0f = floorf(iy), z0f = floorf(iz);
    float fx = ix - x0f, fy = iy - y0f, fz = iz - z0f;
    int x0 = (int)x0f, y0 = (int)y0f, z0 = (int)z0f;

    bool vx0 = (x0 >= 0) & (x0 < Ww), vx1 = (x0 + 1 >= 0) & (x0 + 1 < Ww);
    bool vy0 = (y0 >= 0) & (y0 < Hh), vy1 = (y0 + 1 >= 0) & (y0 + 1 < Hh);
    bool vz0 = (z0 >= 0) & (z0 < Dd), vz1 = (z0 + 1 >= 0) & (z0 + 1 < Dd);
    int xc0 = min(max(x0, 0), Ww - 1),     xc1 = min(max(x0 + 1, 0), Ww - 1);
    int yc0 = min(max(y0, 0), Hh - 1),     yc1 = min(max(y0 + 1, 0), Hh - 1);
    int zc0 = min(max(z0, 0), Dd - 1),     zc1 = min(max(z0 + 1, 0), Dd - 1);

    float wx0 = 1.f - fx, wx1 = fx;
    float wy0 = 1.f - fy, wy1 = fy;
    float wz0 = 1.f - fz, wz1 = fz;

    int rb00 = zc0 * HW + yc0 * Ww;
    int rb01 = zc0 * HW + yc1 * Ww;
    int rb10 = zc1 * HW + yc0 * Ww;
    int rb11 = zc1 * HW + yc1 * Ww;

    off[0] = rb00 + xc0; off[1] = rb00 + xc1;
    off[2] = rb01 + xc0; off[3] = rb01 + xc1;
    off[4] = rb10 + xc0; off[5] = rb10 + xc1;
    off[6] = rb11 + xc0; off[7] = rb11 + xc1;

    wgt[0] = (vx0 & vy0 & vz0) ? wx0 * wy0 * wz0 : 0.f;
    wgt[1] = (vx1 & vy0 & vz0) ? wx1 * wy0 * wz0 : 0.f;
    wgt[2] = (vx0 & vy1 & vz0) ? wx0 * wy1 * wz0 : 0.f;
    wgt[3] = (vx1 & vy1 & vz0) ? wx1 * wy1 * wz0 : 0.f;
    wgt[4] = (vx0 & vy0 & vz1) ? wx0 * wy0 * wz1 : 0.f;
    wgt[5] = (vx1 & vy0 & vz1) ? wx1 * wy0 * wz1 : 0.f;
    wgt[6] = (vx0 & vy1 & vz1) ? wx0 * wy1 * wz1 : 0.f;
    wgt[7] = (vx1 & vy1 & vz1) ? wx1 * wy1 * wz1 : 0.f;
}

// ---------------------------------------------------------------------------
// Kernel 2: fused gather. Block = 256 threads, 64 voxels.
// Phase 1 (threads 0..63): corners once -> smem int4 per corner-PAIR
//   {off_even, off_odd, w_even, w_odd}; also gather sdf/occ + write grid.
// Phase 2 (all 256): task = (voxel, t8 0..7). Lanes t8<4 take even corner,
//   t8>=4 odd corner; lane loads 16B (8 fp16 channels) -> the warp covers
//   both corners of a pair in ONE 128B line per voxel. 4 pairs, then
//   shfl.xor(4) combines even/odd partial sums. Staged via smem for
//   coalesced channel-major output.
// ---------------------------------------------------------------------------
__global__ void __launch_bounds__(256)
feat_gather_kernel(float* __restrict__ out) {
    __shared__ int4  s_ow[VPB][4];     // {off_e, off_o, wgt_e, wgt_o} per pair
    __shared__ float s[VPB][33];

    int b   = blockIdx.y;
    int n0  = blockIdx.x * VPB;
    int tid = threadIdx.x;

    if (tid < VPB) {
        int n = n0 + tid;
        int w = n % Ww;
        int h = (n / Ww) % Hh;
        int d = n / HW;
        int off[8]; float wgt[8]; float ix, iy, iz;
        corners(g_M[b], w, h, d, off, wgt, ix, iy, iz);
        #pragma unroll
        for (int j = 0; j < 4; j++)
            s_ow[tid][j] = make_int4(off[2 * j], off[2 * j + 1],
                                     __float_as_int(wgt[2 * j]),
                                     __float_as_int(wgt[2 * j + 1]));

        // sdf/occ gather (registers)
        const float2* so = g_soT + (size_t)b * DHW;
        float as = 0.f, ao = 0.f;
        #pragma unroll
        for (int k = 0; k < 8; k++) {
            float2 v = __ldg(so + off[k]);
            as = fmaf(wgt[k], v.x, as);
            ao = fmaf(wgt[k], v.y, ao);
        }
        out[FEATN + (size_t)b * DHW + n]        = as;
        out[FEATN + SDFN + (size_t)b * DHW + n] = ao;

        // grid output [B,D,H,W,3]
        float* g = out + FEATN + 2 * SDFN + ((size_t)b * DHW + n) * 3;
        g[0] = 2.0f * ix * (1.0f / 95.0f) - 1.0f;
        g[1] = 2.0f * iy * (1.0f / 95.0f) - 1.0f;
        g[2] = 2.0f * iz * (1.0f / 47.0f) - 1.0f;
    }
    __syncthreads();

    const char* fT = (const char*)g_featT + (size_t)b * DHW * (Cn * 2);
    #pragma unroll
    for (int r = 0; r < VPB * 8 / 256; r++) {       // 2 rounds
        int task = r * 256 + tid;
        int vl = task >> 3;         // voxel 0..63
        int t8 = task & 7;          // lane role
        bool odd = t8 >= 4;
        int lane16 = (t8 & 3) * 16; // 16B chunk within the 64B corner row

        float acc[8];
        #pragma unroll
        for (int i = 0; i < 8; i++) acc[i] = 0.f;

        #pragma unroll
        for (int j = 0; j < 4; j++) {
            int4 ow = s_ow[vl][j];
            int   o  = odd ? ow.y : ow.x;
            float wk = __int_as_float(odd ? ow.w : ow.z);
            uint4 u = __ldg((const uint4*)(fT + (size_t)o * (Cn * 2) + lane16));
            float2 f0 = __half22float2(*(const __half2*)&u.x);
            float2 f1 = __half22float2(*(const __half2*)&u.y);
            float2 f2 = __half22float2(*(const __half2*)&u.z);
            float2 f3 = __half22float2(*(const __half2*)&u.w);
            acc[0] = fmaf(wk, f0.x, acc[0]); acc[1] = fmaf(wk, f0.y, acc[1]);
            acc[2] = fmaf(wk, f1.x, acc[2]); acc[3] = fmaf(wk, f1.y, acc[3]);
            acc[4] = fmaf(wk, f2.x, acc[4]); acc[5] = fmaf(wk, f2.y, acc[5]);
            acc[6] = fmaf(wk, f3.x, acc[6]); acc[7] = fmaf(wk, f3.y, acc[7]);
        }

        // combine even/odd corner partials (lanes t8 and t8^4 share voxel)
        #pragma unroll
        for (int i = 0; i < 8; i++)
            acc[i] += __shfl_xor_sync(0xffffffffu, acc[i], 4);

        if (!odd) {
            int c0 = t8 * 8;        // t8 in 0..3 -> channels t8*8..t8*8+7
            #pragma unroll
            for (int i = 0; i < 8; i++)
                s[vl][c0 + i] = acc[i];
        }
    }
    __syncthreads();

    // coalesced channel-major stores: 64 voxels x 32 ch = 2048 floats
    float* ob = out + (size_t)b * Cn * DHW + n0;
    #pragma unroll
    for (int i = 0; i < VPB * Cn / 256; i++) {      // 8 rounds
        int idx = i * 256 + tid;
        int nl = idx & (VPB - 1);
        int c  = idx >> 6;
        ob[(size_t)c * DHW + nl] = s[nl][c];
    }
}

extern "C" void kernel_launch(void* const* d_in, const int* in_sizes, int n_in,
                              void* d_out, int out_size) {
    const float* feat = (const float*)d_in[0];
    const float* sdf  = (const float*)d_in[1];
    const float* occ  = (const float*)d_in[2];
    const float* hist = (const float*)d_in[3];
    const float* cur  = (const float*)d_in[4];
    float* out = (float*)d_out;

    setup_kernel<<<1, Bn>>>(hist, cur);

    dim3 gT(DHW / 64, Bn);                 // 6912 x 8
    transpose_kernel<<<gT, 256>>>(feat);

    int ib = (int)((SDFN + 255) / 256);
    interleave_kernel<<<ib, 256>>>(sdf, occ);

    dim3 gG(DHW / VPB, Bn);                // 6912 x 8
    feat_gather_kernel<<<gG, 256>>>(out);
}

// round 15
// speedup vs baseline: 1.5656x; 1.5656x over previous
#include <cuda_runtime.h>
#include <cuda_fp16.h>
#include <cuda_bf16.h>

// PoseProjection: fused rigid-transform trilinear resample.
// CROP = (X=96, Y=96, Z=48), B=8, C=32, VOXEL_SIZE=0.0625 (1/v = 16).
// (ix,iy,iz) = T[:3,:3]*(w,h,d) + T[:3,3]*16,  T = inv(current)@historical.
// Output (concat f32): feat[8,32,48,96,96] | sdf | occ | grid[8,48,96,96,3]
//
// featT fp16 channel-last [B,DHW,32] (64B/voxel, 64B-aligned): gather uses
// the R13 mapping (warp = 4 voxels x 8 ch-lanes, 8B/lane) -> exactly 1 L1
// line per (voxel, corner). fp16 only cuts DRAM traffic, not wavefronts.

#define Bn   8
#define Cn   32
#define Dd   48
#define Hh   96
#define Ww   96
#define HW   (Hh * Ww)          // 9216
#define DHW  (Dd * HW)          // 442368
#define FEATN ((size_t)Bn * Cn * DHW)
#define SDFN  ((size_t)Bn * DHW)

#define VPB  64                 // voxels per block (feat_gather)

__device__ float  g_M[Bn][12];
__device__ __half g_featT[(size_t)Bn * DHW * Cn];    // [B][DHW][32] fp16
__device__ float2 g_soT[(size_t)Bn * DHW];           // [B][DHW] {sdf, occ}

// ---------------------------------------------------------------------------
// Setup: T = inv(current) @ historical (Gauss-Jordan w/ pivoting).
// ---------------------------------------------------------------------------
__global__ void setup_kernel(const float* __restrict__ hist,
                             const float* __restrict__ cur) {
    int b = threadIdx.x;
    if (b >= Bn) return;

    float A[4][4], Inv[4][4];
    for (int i = 0; i < 4; i++)
        for (int j = 0; j < 4; j++) {
            A[i][j]   = cur[b * 16 + i * 4 + j];
            Inv[i][j] = (i == j) ? 1.f : 0.f;
        }
    for (int c = 0; c < 4; c++) {
        int p = c; float mx = fabsf(A[c][c]);
        for (int r = c + 1; r < 4; r++) {
            float v = fabsf(A[r][c]);
            if (v > mx) { mx = v; p = r; }
        }
        if (p != c)
            for (int j = 0; j < 4; j++) {
                float t = A[c][j]; A[c][j] = A[p][j]; A[p][j] = t;
                t = Inv[c][j]; Inv[c][j] = Inv[p][j]; Inv[p][j] = t;
            }
        float f = 1.0f / A[c][c];
        for (int j = 0; j < 4; j++) { A[c][j] *= f; Inv[c][j] *= f; }
        for (int r = 0; r < 4; r++) {
            if (r == c) continue;
            float g = A[r][c];
            for (int j = 0; j < 4; j++) {
                A[r][j]   -= g * A[c][j];
                Inv[r][j] -= g * Inv[c][j];
            }
        }
    }
    for (int i = 0; i < 3; i++)
        for (int j = 0; j < 4; j++) {
            float s = 0.f;
            for (int k = 0; k < 4; k++)
                s += Inv[i][k] * hist[b * 16 + k * 4 + j];
            g_M[b][i * 4 + j] = (j == 3) ? s * 16.0f : s;
        }
}

// ---------------------------------------------------------------------------
// Kernel 1: transpose feat [B,32,DHW] f32 -> featT [B,DHW,32] f16, and
// interleave sdf/occ -> float2 for the same 64-voxel tile.
// ---------------------------------------------------------------------------
__global__ void __launch_bounds__(256)
transpose_kernel(const float* __restrict__ feat,
                 const float* __restrict__ sdf,
                 const float* __restrict__ occ) {
    __shared__ float s[32][65];
    int b  = blockIdx.y;
    int n0 = blockIdx.x * 64;
    int tid = threadIdx.x;

    // load: thread (r = channel, q): two float4 -> 8 voxels
    {
        int r = tid >> 3;           // 0..31
        int q = tid & 7;            // 0..7
        const float* fp = feat + (size_t)b * Cn * DHW + (size_t)r * DHW + n0 + q * 8;
        float4 v0 = *(const float4*)(fp);
        float4 v1 = *(const float4*)(fp + 4);
        s[r][q * 8 + 0] = v0.x; s[r][q * 8 + 1] = v0.y;
        s[r][q * 8 + 2] = v0.z; s[r][q * 8 + 3] = v0.w;
        s[r][q * 8 + 4] = v1.x; s[r][q * 8 + 5] = v1.y;
        s[r][q * 8 + 6] = v1.z; s[r][q * 8 + 7] = v1.w;
    }

    // fused sdf/occ interleave (independent of the smem tile)
    if (tid < 64) {
        size_t idx = (size_t)b * DHW + n0 + tid;
        g_soT[idx] = make_float2(sdf[idx], occ[idx]);
    }
    __syncthreads();

    // store: thread (vox 0..63, part 0..3): 8 channels -> 8 halves = 16B
    {
        int vox  = tid >> 2;        // 0..63
        int part = tid & 3;         // 0..3
        int c0 = part * 8;
        __half2 h[4];
        #pragma unroll
        for (int i = 0; i < 4; i++)
            h[i] = __floats2half2_rn(s[c0 + 2 * i][vox], s[c0 + 2 * i + 1][vox]);
        uint4 u = make_uint4(*(unsigned*)&h[0], *(unsigned*)&h[1],
                             *(unsigned*)&h[2], *(unsigned*)&h[3]);
        char* dst = (char*)g_featT + ((size_t)b * DHW + n0 + vox) * (Cn * 2) + part * 16;
        *(uint4*)dst = u;
    }
}

// ---------------------------------------------------------------------------
// Corner computation.
// ---------------------------------------------------------------------------
__device__ __forceinline__ void corners(const float* __restrict__ M,
                                        int w, int h, int d,
                                        int off[8], float wgt[8],
                                        float& ix, float& iy, float& iz) {
    float fw = (float)w, fh = (float)h, fd = (float)d;
    ix = fmaf(M[0], fw, fmaf(M[1], fh, fmaf(M[2],  fd, M[3])));
    iy = fmaf(M[4], fw, fmaf(M[5], fh, fmaf(M[6],  fd, M[7])));
    iz = fmaf(M[8], fw, fmaf(M[9], fh, fmaf(M[10], fd, M[11])));

    float x0f = floorf(ix), y0f = floorf(iy), z0f = floorf(iz);
    float fx = ix - x0f, fy = iy - y0f, fz = iz - z0f;
    int x0 = (int)x0f, y0 = (int)y0f, z0 = (int)z0f;

    bool vx0 = (x0 >= 0) & (x0 < Ww), vx1 = (x0 + 1 >= 0) & (x0 + 1 < Ww);
    bool vy0 = (y0 >= 0) & (y0 < Hh), vy1 = (y0 + 1 >= 0) & (y0 + 1 < Hh);
    bool vz0 = (z0 >= 0) & (z0 < Dd), vz1 = (z0 + 1 >= 0) & (z0 + 1 < Dd);
    int xc0 = min(max(x0, 0), Ww - 1),     xc1 = min(max(x0 + 1, 0), Ww - 1);
    int yc0 = min(max(y0, 0), Hh - 1),     yc1 = min(max(y0 + 1, 0), Hh - 1);
    int zc0 = min(max(z0, 0), Dd - 1),     zc1 = min(max(z0 + 1, 0), Dd - 1);

    float wx0 = 1.f - fx, wx1 = fx;
    float wy0 = 1.f - fy, wy1 = fy;
    float wz0 = 1.f - fz, wz1 = fz;

    int rb00 = zc0 * HW + yc0 * Ww;
    int rb01 = zc0 * HW + yc1 * Ww;
    int rb10 = zc1 * HW + yc0 * Ww;
    int rb11 = zc1 * HW + yc1 * Ww;

    off[0] = rb00 + xc0; off[1] = rb00 + xc1;
    off[2] = rb01 + xc0; off[3] = rb01 + xc1;
    off[4] = rb10 + xc0; off[5] = rb10 + xc1;
    off[6] = rb11 + xc0; off[7] = rb11 + xc1;

    wgt[0] = (vx0 & vy0 & vz0) ? wx0 * wy0 * wz0 : 0.f;
    wgt[1] = (vx1 & vy0 & vz0) ? wx1 * wy0 * wz0 : 0.f;
    wgt[2] = (vx0 & vy1 & vz0) ? wx0 * wy1 * wz0 : 0.f;
    wgt[3] = (vx1 & vy1 & vz0) ? wx1 * wy1 * wz0 : 0.f;
    wgt[4] = (vx0 & vy0 & vz1) ? wx0 * wy0 * wz1 : 0.f;
    wgt[5] = (vx1 & vy0 & vz1) ? wx1 * wy0 * wz1 : 0.f;
    wgt[6] = (vx0 & vy1 & vz1) ? wx0 * wy1 * wz1 : 0.f;
    wgt[7] = (vx1 & vy1 & vz1) ? wx1 * wy1 * wz1 : 0.f;
}

// ---------------------------------------------------------------------------
// Kernel 2: fused gather. Block = 256 threads, 64 voxels.
// Phase 1 (threads 0..63): corners once per voxel -> smem int4 pairs;
//   with corner data in registers also gather sdf/occ + write grid.
// Phase 2 (all 256): task = (voxel, ch4). Lane loads uint2 (4 fp16 ch) per
//   corner; 8 lanes/voxel cover the 64B row -> 1 L1 line per (voxel,corner).
//   Staged via smem so channel-major output stores stay coalesced.
// ---------------------------------------------------------------------------
__global__ void __launch_bounds__(256)
feat_gather_kernel(float* __restrict__ out) {
    __shared__ int4  s_ow[VPB][4];     // {off_e, off_o, wgt_e, wgt_o} per pair
    __shared__ float s[VPB][33];

    int b   = blockIdx.y;
    int n0  = blockIdx.x * VPB;
    int tid = threadIdx.x;

    if (tid < VPB) {
        int n = n0 + tid;
        int w = n % Ww;
        int h = (n / Ww) % Hh;
        int d = n / HW;
        int off[8]; float wgt[8]; float ix, iy, iz;
        corners(g_M[b], w, h, d, off, wgt, ix, iy, iz);
        #pragma unroll
        for (int j = 0; j < 4; j++)
            s_ow[tid][j] = make_int4(off[2 * j], off[2 * j + 1],
                                     __float_as_int(wgt[2 * j]),
                                     __float_as_int(wgt[2 * j + 1]));

        // sdf/occ gather (registers)
        const float2* so = g_soT + (size_t)b * DHW;
        float as = 0.f, ao = 0.f;
        #pragma unroll
        for (int k = 0; k < 8; k++) {
            float2 v = __ldg(so + off[k]);
            as = fmaf(wgt[k], v.x, as);
            ao = fmaf(wgt[k], v.y, ao);
        }
        out[FEATN + (size_t)b * DHW + n]        = as;
        out[FEATN + SDFN + (size_t)b * DHW + n] = ao;

        // grid output [B,D,H,W,3]
        float* g = out + FEATN + 2 * SDFN + ((size_t)b * DHW + n) * 3;
        g[0] = 2.0f * ix * (1.0f / 95.0f) - 1.0f;
        g[1] = 2.0f * iy * (1.0f / 95.0f) - 1.0f;
        g[2] = 2.0f * iz * (1.0f / 47.0f) - 1.0f;
    }
    __syncthreads();

    const char* fT = (const char*)g_featT + (size_t)b * DHW * (Cn * 2);
    #pragma unroll
    for (int r = 0; r < VPB * 8 / 256; r++) {       // 2 rounds
        int task = r * 256 + tid;
        int vl  = task >> 3;        // voxel 0..63
        int ch4 = task & 7;         // channel group 0..7

        float a0 = 0.f, a1 = 0.f, a2 = 0.f, a3 = 0.f;
        #pragma unroll
        for (int j = 0; j < 4; j++) {
            int4 ow = s_ow[vl][j];
            {   // even corner
                uint2 u = __ldg((const uint2*)(fT + (size_t)ow.x * (Cn * 2) + ch4 * 8));
                float wk = __int_as_float(ow.z);
                float2 f0 = __half22float2(*(const __half2*)&u.x);
                float2 f1 = __half22float2(*(const __half2*)&u.y);
                a0 = fmaf(wk, f0.x, a0); a1 = fmaf(wk, f0.y, a1);
                a2 = fmaf(wk, f1.x, a2); a3 = fmaf(wk, f1.y, a3);
            }
            {   // odd corner
                uint2 u = __ldg((const uint2*)(fT + (size_t)ow.y * (Cn * 2) + ch4 * 8));
                float wk = __int_as_float(ow.w);
                float2 f0 = __half22float2(*(const __half2*)&u.x);
                float2 f1 = __half22float2(*(const __half2*)&u.y);
                a0 = fmaf(wk, f0.x, a0); a1 = fmaf(wk, f0.y, a1);
                a2 = fmaf(wk, f1.x, a2); a3 = fmaf(wk, f1.y, a3);
            }
        }
        int cb = ch4 * 4;
        s[vl][cb + 0] = a0;
        s[vl][cb + 1] = a1;
        s[vl][cb + 2] = a2;
        s[vl][cb + 3] = a3;
    }
    __syncthreads();

    // coalesced channel-major stores: 64 voxels x 32 ch = 2048 floats
    float* ob = out + (size_t)b * Cn * DHW + n0;
    #pragma unroll
    for (int i = 0; i < VPB * Cn / 256; i++) {      // 8 rounds
        int idx = i * 256 + tid;
        int nl = idx & (VPB - 1);
        int c  = idx >> 6;
        ob[(size_t)c * DHW + nl] = s[nl][c];
    }
}

extern "C" void kernel_launch(void* const* d_in, const int* in_sizes, int n_in,
                              void* d_out, int out_size) {
    const float* feat = (const float*)d_in[0];
    const float* sdf  = (const float*)d_in[1];
    const float* occ  = (const float*)d_in[2];
    const float* hist = (const float*)d_in[3];
    const float* cur  = (const float*)d_in[4];
    float* out = (float*)d_out;

    setup_kernel<<<1, Bn>>>(hist, cur);

    dim3 gT(DHW / 64, Bn);                 // 6912 x 8
    transpose_kernel<<<gT, 256>>>(feat, sdf, occ);

    dim3 gG(DHW / VPB, Bn);                // 6912 x 8
    feat_gather_kernel<<<gG, 256>>>(out);
}